// round 14
// baseline (speedup 1.0000x reference)
#include <cuda_runtime.h>
#include <cuda_fp16.h>
#include <cstdint>

#define N_NODES  10000
#define N_EDGES  320000
#define IN_DIM   256
#define HIDDEN   256
#define OUT_DIM  128
#define CAP      96     // per-node bucket capacity; max degree ~56 (11σ margin)
#define CHUNK0   4992   // 64-aligned row split for the spmm1/gemm2 pipeline

// ---------------- device scratch (static) ----------------
// g_cnt starts zero (static init); spmm2 re-zeroes it each invocation.
__device__ int    g_cnt[N_NODES];
__device__ int2   g_bucket[N_NODES * CAP];                  // {src, float bits of val}
__device__ __align__(16) __half g_Y0h[N_NODES * HIDDEN];    // fp16(X @ W0)
__device__ __align__(16) __half g_Hh [N_NODES * HIDDEN];    // fp16 relu(A @ Y0)
__device__ __align__(16) __half g_Y1h[N_NODES * OUT_DIM];   // fp16(H @ W1)

// ---------------- bucket scatter (R7-proven) ----------------
__global__ void scatter_kernel(const void* __restrict__ src,
                               const void* __restrict__ dst,
                               const float* __restrict__ val) {
    __shared__ int sh_is64;
    int tid = threadIdx.x;
    if (tid < 32) {
        const int* w = (const int*)src;
        int bad = (w[2 * tid + 1] != 0) || (w[2 * (tid + 32) + 1] != 0);
        int all_zero = __all_sync(0xFFFFFFFFu, !bad);
        if (tid == 0) sh_is64 = all_zero;
    }
    __syncthreads();
    int is64 = sh_is64;

    int e = blockIdx.x * blockDim.x + tid;
    if (e < N_EDGES) {
        int d, s;
        if (is64) {
            d = (int)((const long long*)dst)[e];
            s = (int)((const long long*)src)[e];
        } else {
            d = ((const int*)dst)[e];
            s = ((const int*)src)[e];
        }
        int pos = atomicAdd(&g_cnt[d], 1);
        if (pos < CAP)
            g_bucket[d * CAP + pos] = make_int2(s, __float_as_int(val[e]));
    }
}

// ---------------- tf32 MMA helpers (R5-R13 proven) ----------------
__device__ __forceinline__ uint32_t f2tf32(float x) {
    uint32_t r;
    asm("cvt.rna.tf32.f32 %0, %1;" : "=r"(r) : "f"(x));
    return r;
}

__device__ __forceinline__ void mma_tf32(float* d, const uint32_t* a,
                                         const uint32_t* b, const float* c) {
    asm("mma.sync.aligned.m16n8k8.row.col.f32.tf32.tf32.f32 "
        "{%0,%1,%2,%3},{%4,%5,%6,%7},{%8,%9},{%10,%11,%12,%13};"
        : "=f"(d[0]), "=f"(d[1]), "=f"(d[2]), "=f"(d[3])
        : "r"(a[0]), "r"(a[1]), "r"(a[2]), "r"(a[3]),
          "r"(b[0]), "r"(b[1]),
          "f"(c[0]), "f"(c[1]), "f"(c[2]), "f"(c[3]));
}

#define SA 36   // As[m][k] stride (uint32)
#define SB 72   // Bs[k][n] stride (uint32)

// R9-verbatim compute: 4 warps 2m x 2n, warp tile 32x32, BK=32 (4 x k8 steps)
__device__ __forceinline__ void gemm_compute(const uint32_t* As1, const uint32_t* Bs1,
                                             int wm, int wn, int lane,
                                             float acc[2][4][4]) {
    #pragma unroll
    for (int ks = 0; ks < 4; ks++) {
        int kk = ks * 8;
        uint32_t bf[4][2];
        #pragma unroll
        for (int nf = 0; nf < 4; nf++) {
            int n = wn + nf * 8 + (lane >> 2);
            bf[nf][0] = Bs1[(kk + (lane & 3)) * SB + n];
            bf[nf][1] = Bs1[(kk + 4 + (lane & 3)) * SB + n];
        }
        #pragma unroll
        for (int mf = 0; mf < 2; mf++) {
            int m = wm + mf * 16 + (lane >> 2);
            uint32_t af[4];
            af[0] = As1[m * SA + kk + (lane & 3)];
            af[1] = As1[(m + 8) * SA + kk + (lane & 3)];
            af[2] = As1[m * SA + kk + 4 + (lane & 3)];
            af[3] = As1[(m + 8) * SA + kk + 4 + (lane & 3)];
            #pragma unroll
            for (int nf = 0; nf < 4; nf++)
                mma_tf32(acc[mf][nf], af, bf[nf], acc[mf][nf]);
        }
    }
}

// R9-verbatim epilogue: fp32 acc -> fp16 pairs into C[M][N] (rows < m_end)
__device__ __forceinline__ void gemm_epilogue(__half* __restrict__ C, int m_end, int N,
                                              int bm, int bn, int wm, int wn,
                                              int lane, float acc[2][4][4]) {
    #pragma unroll
    for (int mf = 0; mf < 2; mf++) {
        int r0 = bm + wm + mf * 16 + (lane >> 2);
        #pragma unroll
        for (int nf = 0; nf < 4; nf++) {
            int c0 = bn + wn + nf * 8 + 2 * (lane & 3);
            if (r0 < m_end)
                *(__half2*)&C[(size_t)r0 * N + c0] =
                    __floats2half2_rn(acc[mf][nf][0], acc[mf][nf][1]);
            if (r0 + 8 < m_end)
                *(__half2*)&C[(size_t)(r0 + 8) * N + c0] =
                    __floats2half2_rn(acc[mf][nf][2], acc[mf][nf][3]);
        }
    }
}

// GEMM1 (R13-verbatim): A fp32 [M][256], B fp32 [256][N] -> C fp16
__global__ __launch_bounds__(128) void gemm_XW0_kernel(const float* __restrict__ A,
                                                       const float* __restrict__ B, int M) {
    const int N = HIDDEN;
    __shared__ __align__(16) uint32_t As[2][64 * SA];
    __shared__ __align__(16) uint32_t Bs[2][32 * SB];

    int tid  = threadIdx.x;
    int lane = tid & 31;
    int wid  = tid >> 5;
    int wm = (wid & 1) * 32;
    int wn = (wid >> 1) * 32;
    int bm = blockIdx.y * 64;
    int bn = blockIdx.x * 64;

    int a_kf = tid & 7;
    int a_m0 = tid >> 3;
    int b_nq = tid & 15;
    int b_k0 = tid >> 4;

    float acc[2][4][4] = {};
    float4 ar[4], br[4];

    #pragma unroll
    for (int it = 0; it < 4; it++) {
        int gr = bm + a_m0 + it * 16;
        ar[it] = (gr < M) ? *(const float4*)&A[(size_t)gr * 256 + a_kf * 4]
                          : make_float4(0.f, 0.f, 0.f, 0.f);
        br[it] = *(const float4*)&B[(size_t)(b_k0 + it * 8) * N + bn + b_nq * 4];
    }

    #pragma unroll
    for (int k0 = 0; k0 < 8; k0++) {
        int cur = k0 & 1;
        #pragma unroll
        for (int it = 0; it < 4; it++) {
            int m = a_m0 + it * 16;
            *(uint4*)&As[cur][m * SA + a_kf * 4] =
                make_uint4(f2tf32(ar[it].x), f2tf32(ar[it].y),
                           f2tf32(ar[it].z), f2tf32(ar[it].w));
            int k = b_k0 + it * 8;
            *(uint4*)&Bs[cur][k * SB + b_nq * 4] =
                make_uint4(f2tf32(br[it].x), f2tf32(br[it].y),
                           f2tf32(br[it].z), f2tf32(br[it].w));
        }
        __syncthreads();

        if (k0 < 7) {
            int kb = (k0 + 1) * 32;
            #pragma unroll
            for (int it = 0; it < 4; it++) {
                int gr = bm + a_m0 + it * 16;
                ar[it] = (gr < M) ? *(const float4*)&A[(size_t)gr * 256 + kb + a_kf * 4]
                                  : make_float4(0.f, 0.f, 0.f, 0.f);
                br[it] = *(const float4*)&B[(size_t)(kb + b_k0 + it * 8) * N + bn + b_nq * 4];
            }
        }

        gemm_compute(As[cur], Bs[cur], wm, wn, lane, acc);
        __syncthreads();
    }

    gemm_epilogue(g_Y0h, M, N, bm, bn, wm, wn, lane, acc);
}

// GEMM2 (R13-verbatim + row_base/m_end): A fp16 (g_Hh), B fp32 -> C fp16
__global__ __launch_bounds__(128) void gemm_HW1_kernel(const float* __restrict__ B,
                                                       int row_base, int m_end) {
    const int N = OUT_DIM;
    __shared__ __align__(16) uint32_t As[2][64 * SA];
    __shared__ __align__(16) uint32_t Bs[2][32 * SB];

    int tid  = threadIdx.x;
    int lane = tid & 31;
    int wid  = tid >> 5;
    int wm = (wid & 1) * 32;
    int wn = (wid >> 1) * 32;
    int bm = row_base + blockIdx.y * 64;
    int bn = blockIdx.x * 64;

    int a_kf = tid & 3;       // k uint4 index (k = 8*a_kf)
    int a_m0 = tid >> 2;      // 0..31, rows m0, m0+32
    int b_nq = tid & 15;
    int b_k0 = tid >> 4;

    float acc[2][4][4] = {};
    uint4  ar[2];
    float4 br[4];

    #pragma unroll
    for (int it = 0; it < 2; it++) {
        int gr = bm + a_m0 + it * 32;
        ar[it] = (gr < m_end) ? *(const uint4*)&g_Hh[(size_t)gr * 256 + a_kf * 8]
                              : make_uint4(0, 0, 0, 0);
    }
    #pragma unroll
    for (int it = 0; it < 4; it++)
        br[it] = *(const float4*)&B[(size_t)(b_k0 + it * 8) * N + bn + b_nq * 4];

    #pragma unroll
    for (int k0 = 0; k0 < 8; k0++) {
        int cur = k0 & 1;
        #pragma unroll
        for (int it = 0; it < 2; it++) {
            int m = a_m0 + it * 32;
            const __half2* hp = (const __half2*)&ar[it];
            float2 f0 = __half22float2(hp[0]);
            float2 f1 = __half22float2(hp[1]);
            float2 f2 = __half22float2(hp[2]);
            float2 f3 = __half22float2(hp[3]);
            *(uint4*)&As[cur][m * SA + a_kf * 8] =
                make_uint4(f2tf32(f0.x), f2tf32(f0.y), f2tf32(f1.x), f2tf32(f1.y));
            *(uint4*)&As[cur][m * SA + a_kf * 8 + 4] =
                make_uint4(f2tf32(f2.x), f2tf32(f2.y), f2tf32(f3.x), f2tf32(f3.y));
        }
        #pragma unroll
        for (int it = 0; it < 4; it++) {
            int k = b_k0 + it * 8;
            *(uint4*)&Bs[cur][k * SB + b_nq * 4] =
                make_uint4(f2tf32(br[it].x), f2tf32(br[it].y),
                           f2tf32(br[it].z), f2tf32(br[it].w));
        }
        __syncthreads();

        if (k0 < 7) {
            int kb = (k0 + 1) * 32;
            #pragma unroll
            for (int it = 0; it < 2; it++) {
                int gr = bm + a_m0 + it * 32;
                ar[it] = (gr < m_end) ? *(const uint4*)&g_Hh[(size_t)gr * 256 + kb + a_kf * 8]
                                      : make_uint4(0, 0, 0, 0);
            }
            #pragma unroll
            for (int it = 0; it < 4; it++)
                br[it] = *(const float4*)&B[(size_t)(kb + b_k0 + it * 8) * N + bn + b_nq * 4];
        }

        gemm_compute(As[cur], Bs[cur], wm, wn, lane, acc);
        __syncthreads();
    }

    gemm_epilogue(g_Y1h, m_end, N, bm, bn, wm, wn, lane, acc);
}

// ---------------- bucket SpMMs (R13-proven, warp per row, 2-edge unroll) ----------------
__device__ __forceinline__ void fma_h8(float* a, uint4 r, float v) {
    float2 f0 = __half22float2(*(__half2*)&r.x);
    float2 f1 = __half22float2(*(__half2*)&r.y);
    float2 f2 = __half22float2(*(__half2*)&r.z);
    float2 f3 = __half22float2(*(__half2*)&r.w);
    a[0] = fmaf(v, f0.x, a[0]); a[1] = fmaf(v, f0.y, a[1]);
    a[2] = fmaf(v, f1.x, a[2]); a[3] = fmaf(v, f1.y, a[3]);
    a[4] = fmaf(v, f2.x, a[4]); a[5] = fmaf(v, f2.y, a[5]);
    a[6] = fmaf(v, f3.x, a[6]); a[7] = fmaf(v, f3.y, a[7]);
}

// g_Hh[row] = fp16(relu(A @ Y0h)) for rows [row_base, row_end)
__global__ void spmm1_kernel(int row_base, int row_end) {
    int row = row_base + blockIdx.x * (blockDim.x >> 5) + (threadIdx.x >> 5);
    if (row >= row_end) return;
    int lane = threadIdx.x & 31;
    int deg = g_cnt[row];
    if (deg > CAP) deg = CAP;
    const int2* bk = g_bucket + row * CAP;

    float acc[8] = {};
    int e = 0;
    for (; e + 2 <= deg; e += 2) {
        int2 t0 = bk[e], t1 = bk[e + 1];
        uint4 r0 = *(const uint4*)(g_Y0h + (size_t)t0.x * HIDDEN + lane * 8);
        uint4 r1 = *(const uint4*)(g_Y0h + (size_t)t1.x * HIDDEN + lane * 8);
        fma_h8(acc, r0, __int_as_float(t0.y));
        fma_h8(acc, r1, __int_as_float(t1.y));
    }
    if (e < deg) {
        int2 t0 = bk[e];
        uint4 r0 = *(const uint4*)(g_Y0h + (size_t)t0.x * HIDDEN + lane * 8);
        fma_h8(acc, r0, __int_as_float(t0.y));
    }

    #pragma unroll
    for (int i = 0; i < 8; i++) acc[i] = fmaxf(acc[i], 0.f);
    __half2 h0 = __floats2half2_rn(acc[0], acc[1]);
    __half2 h1 = __floats2half2_rn(acc[2], acc[3]);
    __half2 h2 = __floats2half2_rn(acc[4], acc[5]);
    __half2 h3 = __floats2half2_rn(acc[6], acc[7]);
    *(uint4*)&g_Hh[(size_t)row * HIDDEN + lane * 8] =
        make_uint4(*(uint32_t*)&h0, *(uint32_t*)&h1, *(uint32_t*)&h2, *(uint32_t*)&h3);
}

// out = A @ Y1h. Zero-restores g_cnt.
__global__ void spmm2_kernel(float4* __restrict__ out) {
    int row = blockIdx.x * (blockDim.x >> 5) + (threadIdx.x >> 5);
    if (row >= N_NODES) return;
    int lane = threadIdx.x & 31;
    int deg = g_cnt[row];
    if (deg > CAP) deg = CAP;
    const int2* bk = g_bucket + row * CAP;

    float acc[4] = {};
    int e = 0;
    for (; e + 2 <= deg; e += 2) {
        int2 t0 = bk[e], t1 = bk[e + 1];
        uint2 r0 = *(const uint2*)(g_Y1h + (size_t)t0.x * OUT_DIM + lane * 4);
        uint2 r1 = *(const uint2*)(g_Y1h + (size_t)t1.x * OUT_DIM + lane * 4);
        float v0 = __int_as_float(t0.y), v1 = __int_as_float(t1.y);
        float2 a0 = __half22float2(*(__half2*)&r0.x);
        float2 a1 = __half22float2(*(__half2*)&r0.y);
        float2 b0 = __half22float2(*(__half2*)&r1.x);
        float2 b1 = __half22float2(*(__half2*)&r1.y);
        acc[0] = fmaf(v0, a0.x, acc[0]); acc[1] = fmaf(v0, a0.y, acc[1]);
        acc[2] = fmaf(v0, a1.x, acc[2]); acc[3] = fmaf(v0, a1.y, acc[3]);
        acc[0] = fmaf(v1, b0.x, acc[0]); acc[1] = fmaf(v1, b0.y, acc[1]);
        acc[2] = fmaf(v1, b1.x, acc[2]); acc[3] = fmaf(v1, b1.y, acc[3]);
    }
    if (e < deg) {
        int2 t0 = bk[e];
        uint2 r0 = *(const uint2*)(g_Y1h + (size_t)t0.x * OUT_DIM + lane * 4);
        float v0 = __int_as_float(t0.y);
        float2 a0 = __half22float2(*(__half2*)&r0.x);
        float2 a1 = __half22float2(*(__half2*)&r0.y);
        acc[0] = fmaf(v0, a0.x, acc[0]); acc[1] = fmaf(v0, a0.y, acc[1]);
        acc[2] = fmaf(v0, a1.x, acc[2]); acc[3] = fmaf(v0, a1.y, acc[3]);
    }
    out[(size_t)row * 32 + lane] = make_float4(acc[0], acc[1], acc[2], acc[3]);

    if (lane == 0) g_cnt[row] = 0;   // restore invariant for next invocation
}

// ---------------- launch ----------------
extern "C" void kernel_launch(void* const* d_in, const int* in_sizes, int n_in,
                              void* d_out, int out_size) {
    const float* features = (const float*)d_in[0];
    const void*  edge_src = d_in[1];
    const void*  edge_dst = d_in[2];
    const float* edge_val = (const float*)d_in[3];
    const float* W0       = (const float*)d_in[4];
    const float* W1       = (const float*)d_in[5];
    float4*      out      = (float4*)d_out;

    static cudaStream_t s1 = nullptr, s2 = nullptr;
    static cudaEvent_t  ev_fork = nullptr, ev_y0 = nullptr;
    static cudaEvent_t  ev_h0 = nullptr, ev_g0 = nullptr;
    if (s1 == nullptr) {
        cudaStreamCreateWithFlags(&s1, cudaStreamNonBlocking);
        cudaStreamCreateWithFlags(&s2, cudaStreamNonBlocking);
        cudaEventCreateWithFlags(&ev_fork, cudaEventDisableTiming);
        cudaEventCreateWithFlags(&ev_y0,   cudaEventDisableTiming);
        cudaEventCreateWithFlags(&ev_h0,   cudaEventDisableTiming);
        cudaEventCreateWithFlags(&ev_g0,   cudaEventDisableTiming);
    }

    // Fork: GEMM1 on s1 (independent of edge bucketing)
    cudaEventRecord(ev_fork, 0);
    cudaStreamWaitEvent(s1, ev_fork, 0);
    {
        dim3 grid(HIDDEN / 64, (N_NODES + 63) / 64);
        gemm_XW0_kernel<<<grid, 128, 0, s1>>>(features, W0, N_NODES);
    }
    cudaEventRecord(ev_y0, s1);

    // Main: bucket the edges
    scatter_kernel<<<(N_EDGES + 255) / 256, 256>>>(edge_src, edge_dst, edge_val);

    // Join: spmm1 needs buckets + all of Y0
    cudaStreamWaitEvent(0, ev_y0, 0);

    // Pipelined middle: spmm1(c0) -> {gemm2(c0) on s2 || spmm1(c1) -> gemm2(c1) on main}
    spmm1_kernel<<<(CHUNK0 + 7) / 8, 256>>>(0, CHUNK0);
    cudaEventRecord(ev_h0, 0);

    cudaStreamWaitEvent(s2, ev_h0, 0);
    {
        dim3 grid(OUT_DIM / 64, CHUNK0 / 64);
        gemm_HW1_kernel<<<grid, 128, 0, s2>>>(W1, 0, CHUNK0);
    }
    cudaEventRecord(ev_g0, s2);

    spmm1_kernel<<<(N_NODES - CHUNK0 + 7) / 8, 256>>>(CHUNK0, N_NODES);
    {
        dim3 grid(OUT_DIM / 64, (N_NODES - CHUNK0 + 63) / 64);
        gemm_HW1_kernel<<<grid, 128>>>(W1, CHUNK0, N_NODES);
    }

    // spmm2 needs all of Y1
    cudaStreamWaitEvent(0, ev_g0, 0);
    spmm2_kernel<<<(N_NODES + 7) / 8, 256>>>(out);
}

// round 15
// speedup vs baseline: 1.0647x; 1.0647x over previous
#include <cuda_runtime.h>
#include <cuda_fp16.h>
#include <cstdint>

#define N_NODES  10000
#define N_EDGES  320000
#define IN_DIM   256
#define HIDDEN   256
#define OUT_DIM  128
#define CAP      96     // per-node bucket capacity; max degree ~56 (11σ margin)
#define G1SPLIT  4992   // 64-aligned row split for the two gemm1 halves

// ---------------- device scratch (static) ----------------
// g_cnt starts zero (static init); spmm2 re-zeroes it each invocation.
__device__ int    g_cnt[N_NODES];
__device__ int2   g_bucket[N_NODES * CAP];                  // {src, float bits of val}
__device__ __align__(16) __half g_Y0h[N_NODES * HIDDEN];    // fp16(X @ W0)
__device__ __align__(16) __half g_Hh [N_NODES * HIDDEN];    // fp16 relu(A @ Y0)
__device__ __align__(16) __half g_Y1h[N_NODES * OUT_DIM];   // fp16(H @ W1)

// ---------------- bucket scatter (R7-proven) ----------------
__global__ void scatter_kernel(const void* __restrict__ src,
                               const void* __restrict__ dst,
                               const float* __restrict__ val) {
    __shared__ int sh_is64;
    int tid = threadIdx.x;
    if (tid < 32) {
        const int* w = (const int*)src;
        int bad = (w[2 * tid + 1] != 0) || (w[2 * (tid + 32) + 1] != 0);
        int all_zero = __all_sync(0xFFFFFFFFu, !bad);
        if (tid == 0) sh_is64 = all_zero;
    }
    __syncthreads();
    int is64 = sh_is64;

    int e = blockIdx.x * blockDim.x + tid;
    if (e < N_EDGES) {
        int d, s;
        if (is64) {
            d = (int)((const long long*)dst)[e];
            s = (int)((const long long*)src)[e];
        } else {
            d = ((const int*)dst)[e];
            s = ((const int*)src)[e];
        }
        int pos = atomicAdd(&g_cnt[d], 1);
        if (pos < CAP)
            g_bucket[d * CAP + pos] = make_int2(s, __float_as_int(val[e]));
    }
}

// ---------------- tf32 MMA helpers (R5-R13 proven) ----------------
__device__ __forceinline__ uint32_t f2tf32(float x) {
    uint32_t r;
    asm("cvt.rna.tf32.f32 %0, %1;" : "=r"(r) : "f"(x));
    return r;
}

__device__ __forceinline__ void mma_tf32(float* d, const uint32_t* a,
                                         const uint32_t* b, const float* c) {
    asm("mma.sync.aligned.m16n8k8.row.col.f32.tf32.tf32.f32 "
        "{%0,%1,%2,%3},{%4,%5,%6,%7},{%8,%9},{%10,%11,%12,%13};"
        : "=f"(d[0]), "=f"(d[1]), "=f"(d[2]), "=f"(d[3])
        : "r"(a[0]), "r"(a[1]), "r"(a[2]), "r"(a[3]),
          "r"(b[0]), "r"(b[1]),
          "f"(c[0]), "f"(c[1]), "f"(c[2]), "f"(c[3]));
}

#define SA 36   // As[m][k] stride (uint32)
#define SB 72   // Bs[k][n] stride (uint32)

// R9-verbatim compute: 4 warps 2m x 2n, warp tile 32x32, BK=32 (4 x k8 steps)
__device__ __forceinline__ void gemm_compute(const uint32_t* As1, const uint32_t* Bs1,
                                             int wm, int wn, int lane,
                                             float acc[2][4][4]) {
    #pragma unroll
    for (int ks = 0; ks < 4; ks++) {
        int kk = ks * 8;
        uint32_t bf[4][2];
        #pragma unroll
        for (int nf = 0; nf < 4; nf++) {
            int n = wn + nf * 8 + (lane >> 2);
            bf[nf][0] = Bs1[(kk + (lane & 3)) * SB + n];
            bf[nf][1] = Bs1[(kk + 4 + (lane & 3)) * SB + n];
        }
        #pragma unroll
        for (int mf = 0; mf < 2; mf++) {
            int m = wm + mf * 16 + (lane >> 2);
            uint32_t af[4];
            af[0] = As1[m * SA + kk + (lane & 3)];
            af[1] = As1[(m + 8) * SA + kk + (lane & 3)];
            af[2] = As1[m * SA + kk + 4 + (lane & 3)];
            af[3] = As1[(m + 8) * SA + kk + 4 + (lane & 3)];
            #pragma unroll
            for (int nf = 0; nf < 4; nf++)
                mma_tf32(acc[mf][nf], af, bf[nf], acc[mf][nf]);
        }
    }
}

// R9-verbatim epilogue: fp32 acc -> fp16 pairs into C[M][N] (rows < m_end)
__device__ __forceinline__ void gemm_epilogue(__half* __restrict__ C, int m_end, int N,
                                              int bm, int bn, int wm, int wn,
                                              int lane, float acc[2][4][4]) {
    #pragma unroll
    for (int mf = 0; mf < 2; mf++) {
        int r0 = bm + wm + mf * 16 + (lane >> 2);
        #pragma unroll
        for (int nf = 0; nf < 4; nf++) {
            int c0 = bn + wn + nf * 8 + 2 * (lane & 3);
            if (r0 < m_end)
                *(__half2*)&C[(size_t)r0 * N + c0] =
                    __floats2half2_rn(acc[mf][nf][0], acc[mf][nf][1]);
            if (r0 + 8 < m_end)
                *(__half2*)&C[(size_t)(r0 + 8) * N + c0] =
                    __floats2half2_rn(acc[mf][nf][2], acc[mf][nf][3]);
        }
    }
}

// GEMM1: A fp32 [*][256] rows [row_base,m_end), B fp32 [256][256] -> Y0h fp16
// BM=64, BN=64, BK=32, 128 threads; ONE sync per k-iter double buffering.
__global__ __launch_bounds__(128) void gemm_XW0_kernel(const float* __restrict__ A,
                                                       const float* __restrict__ B,
                                                       int row_base, int m_end) {
    const int N = HIDDEN;
    __shared__ __align__(16) uint32_t As[2][64 * SA];
    __shared__ __align__(16) uint32_t Bs[2][32 * SB];

    int tid  = threadIdx.x;
    int lane = tid & 31;
    int wid  = tid >> 5;
    int wm = (wid & 1) * 32;
    int wn = (wid >> 1) * 32;
    int bm = row_base + blockIdx.y * 64;
    int bn = blockIdx.x * 64;

    int a_kf = tid & 7;
    int a_m0 = tid >> 3;
    int b_nq = tid & 15;
    int b_k0 = tid >> 4;

    float acc[2][4][4] = {};
    float4 ar[4], br[4];

    // prologue: load + stage tile 0
    #pragma unroll
    for (int it = 0; it < 4; it++) {
        int gr = bm + a_m0 + it * 16;
        ar[it] = (gr < m_end) ? *(const float4*)&A[(size_t)gr * 256 + a_kf * 4]
                              : make_float4(0.f, 0.f, 0.f, 0.f);
        br[it] = *(const float4*)&B[(size_t)(b_k0 + it * 8) * N + bn + b_nq * 4];
    }
    #pragma unroll
    for (int it = 0; it < 4; it++) {
        int m = a_m0 + it * 16;
        *(uint4*)&As[0][m * SA + a_kf * 4] =
            make_uint4(f2tf32(ar[it].x), f2tf32(ar[it].y),
                       f2tf32(ar[it].z), f2tf32(ar[it].w));
        int k = b_k0 + it * 8;
        *(uint4*)&Bs[0][k * SB + b_nq * 4] =
            make_uint4(f2tf32(br[it].x), f2tf32(br[it].y),
                       f2tf32(br[it].z), f2tf32(br[it].w));
    }
    __syncthreads();

    #pragma unroll
    for (int k0 = 0; k0 < 8; k0++) {
        int cur = k0 & 1;
        // issue next tile's global loads (long latency overlaps compute)
        if (k0 < 7) {
            int kb = (k0 + 1) * 32;
            #pragma unroll
            for (int it = 0; it < 4; it++) {
                int gr = bm + a_m0 + it * 16;
                ar[it] = (gr < m_end) ? *(const float4*)&A[(size_t)gr * 256 + kb + a_kf * 4]
                                      : make_float4(0.f, 0.f, 0.f, 0.f);
                br[it] = *(const float4*)&B[(size_t)(kb + b_k0 + it * 8) * N + bn + b_nq * 4];
            }
        }

        gemm_compute(As[cur], Bs[cur], wm, wn, lane, acc);

        // stage next tile into the other buffer (overlaps other warps' MMA)
        if (k0 < 7) {
            #pragma unroll
            for (int it = 0; it < 4; it++) {
                int m = a_m0 + it * 16;
                *(uint4*)&As[1 - cur][m * SA + a_kf * 4] =
                    make_uint4(f2tf32(ar[it].x), f2tf32(ar[it].y),
                               f2tf32(ar[it].z), f2tf32(ar[it].w));
                int k = b_k0 + it * 8;
                *(uint4*)&Bs[1 - cur][k * SB + b_nq * 4] =
                    make_uint4(f2tf32(br[it].x), f2tf32(br[it].y),
                               f2tf32(br[it].z), f2tf32(br[it].w));
            }
            __syncthreads();   // staging done AND compute of overwritten buffer done
        }
    }

    gemm_epilogue(g_Y0h, m_end, N, bm, bn, wm, wn, lane, acc);
}

// GEMM2: A fp16 (g_Hh) [M][256], B fp32 [256][128] -> Y1h fp16; one sync/iter.
__global__ __launch_bounds__(128) void gemm_HW1_kernel(const float* __restrict__ B, int M) {
    const int N = OUT_DIM;
    __shared__ __align__(16) uint32_t As[2][64 * SA];
    __shared__ __align__(16) uint32_t Bs[2][32 * SB];

    int tid  = threadIdx.x;
    int lane = tid & 31;
    int wid  = tid >> 5;
    int wm = (wid & 1) * 32;
    int wn = (wid >> 1) * 32;
    int bm = blockIdx.y * 64;
    int bn = blockIdx.x * 64;

    int a_kf = tid & 3;       // k uint4 index (k = 8*a_kf)
    int a_m0 = tid >> 2;      // 0..31, rows m0, m0+32
    int b_nq = tid & 15;
    int b_k0 = tid >> 4;

    float acc[2][4][4] = {};
    uint4  ar[2];
    float4 br[4];

    // prologue: load + stage tile 0
    #pragma unroll
    for (int it = 0; it < 2; it++) {
        int gr = bm + a_m0 + it * 32;
        ar[it] = (gr < M) ? *(const uint4*)&g_Hh[(size_t)gr * 256 + a_kf * 8]
                          : make_uint4(0, 0, 0, 0);
    }
    #pragma unroll
    for (int it = 0; it < 4; it++)
        br[it] = *(const float4*)&B[(size_t)(b_k0 + it * 8) * N + bn + b_nq * 4];

    #pragma unroll
    for (int it = 0; it < 2; it++) {
        int m = a_m0 + it * 32;
        const __half2* hp = (const __half2*)&ar[it];
        float2 f0 = __half22float2(hp[0]);
        float2 f1 = __half22float2(hp[1]);
        float2 f2 = __half22float2(hp[2]);
        float2 f3 = __half22float2(hp[3]);
        *(uint4*)&As[0][m * SA + a_kf * 8] =
            make_uint4(f2tf32(f0.x), f2tf32(f0.y), f2tf32(f1.x), f2tf32(f1.y));
        *(uint4*)&As[0][m * SA + a_kf * 8 + 4] =
            make_uint4(f2tf32(f2.x), f2tf32(f2.y), f2tf32(f3.x), f2tf32(f3.y));
    }
    #pragma unroll
    for (int it = 0; it < 4; it++) {
        int k = b_k0 + it * 8;
        *(uint4*)&Bs[0][k * SB + b_nq * 4] =
            make_uint4(f2tf32(br[it].x), f2tf32(br[it].y),
                       f2tf32(br[it].z), f2tf32(br[it].w));
    }
    __syncthreads();

    #pragma unroll
    for (int k0 = 0; k0 < 8; k0++) {
        int cur = k0 & 1;
        if (k0 < 7) {
            int kb = (k0 + 1) * 32;
            #pragma unroll
            for (int it = 0; it < 2; it++) {
                int gr = bm + a_m0 + it * 32;
                ar[it] = (gr < M) ? *(const uint4*)&g_Hh[(size_t)gr * 256 + kb + a_kf * 8]
                                  : make_uint4(0, 0, 0, 0);
            }
            #pragma unroll
            for (int it = 0; it < 4; it++)
                br[it] = *(const float4*)&B[(size_t)(kb + b_k0 + it * 8) * N + bn + b_nq * 4];
        }

        gemm_compute(As[cur], Bs[cur], wm, wn, lane, acc);

        if (k0 < 7) {
            #pragma unroll
            for (int it = 0; it < 2; it++) {
                int m = a_m0 + it * 32;
                const __half2* hp = (const __half2*)&ar[it];
                float2 f0 = __half22float2(hp[0]);
                float2 f1 = __half22float2(hp[1]);
                float2 f2 = __half22float2(hp[2]);
                float2 f3 = __half22float2(hp[3]);
                *(uint4*)&As[1 - cur][m * SA + a_kf * 8] =
                    make_uint4(f2tf32(f0.x), f2tf32(f0.y), f2tf32(f1.x), f2tf32(f1.y));
                *(uint4*)&As[1 - cur][m * SA + a_kf * 8 + 4] =
                    make_uint4(f2tf32(f2.x), f2tf32(f2.y), f2tf32(f3.x), f2tf32(f3.y));
            }
            #pragma unroll
            for (int it = 0; it < 4; it++) {
                int k = b_k0 + it * 8;
                *(uint4*)&Bs[1 - cur][k * SB + b_nq * 4] =
                    make_uint4(f2tf32(br[it].x), f2tf32(br[it].y),
                               f2tf32(br[it].z), f2tf32(br[it].w));
            }
            __syncthreads();
        }
    }

    gemm_epilogue(g_Y1h, M, N, bm, bn, wm, wn, lane, acc);
}

// ---------------- bucket SpMMs (R13-verbatim) ----------------
__device__ __forceinline__ void fma_h8(float* a, uint4 r, float v) {
    float2 f0 = __half22float2(*(__half2*)&r.x);
    float2 f1 = __half22float2(*(__half2*)&r.y);
    float2 f2 = __half22float2(*(__half2*)&r.z);
    float2 f3 = __half22float2(*(__half2*)&r.w);
    a[0] = fmaf(v, f0.x, a[0]); a[1] = fmaf(v, f0.y, a[1]);
    a[2] = fmaf(v, f1.x, a[2]); a[3] = fmaf(v, f1.y, a[3]);
    a[4] = fmaf(v, f2.x, a[4]); a[5] = fmaf(v, f2.y, a[5]);
    a[6] = fmaf(v, f3.x, a[6]); a[7] = fmaf(v, f3.y, a[7]);
}

// g_Hh = fp16(relu(A @ Y0h)): each lane covers cols [lane*8, lane*8+8)
__global__ void spmm1_kernel() {
    int row = blockIdx.x * (blockDim.x >> 5) + (threadIdx.x >> 5);
    if (row >= N_NODES) return;
    int lane = threadIdx.x & 31;
    int deg = g_cnt[row];
    if (deg > CAP) deg = CAP;
    const int2* bk = g_bucket + row * CAP;

    float acc[8] = {};
    int e = 0;
    for (; e + 2 <= deg; e += 2) {
        int2 t0 = bk[e], t1 = bk[e + 1];
        uint4 r0 = *(const uint4*)(g_Y0h + (size_t)t0.x * HIDDEN + lane * 8);
        uint4 r1 = *(const uint4*)(g_Y0h + (size_t)t1.x * HIDDEN + lane * 8);
        fma_h8(acc, r0, __int_as_float(t0.y));
        fma_h8(acc, r1, __int_as_float(t1.y));
    }
    if (e < deg) {
        int2 t0 = bk[e];
        uint4 r0 = *(const uint4*)(g_Y0h + (size_t)t0.x * HIDDEN + lane * 8);
        fma_h8(acc, r0, __int_as_float(t0.y));
    }

    #pragma unroll
    for (int i = 0; i < 8; i++) acc[i] = fmaxf(acc[i], 0.f);
    __half2 h0 = __floats2half2_rn(acc[0], acc[1]);
    __half2 h1 = __floats2half2_rn(acc[2], acc[3]);
    __half2 h2 = __floats2half2_rn(acc[4], acc[5]);
    __half2 h3 = __floats2half2_rn(acc[6], acc[7]);
    *(uint4*)&g_Hh[(size_t)row * HIDDEN + lane * 8] =
        make_uint4(*(uint32_t*)&h0, *(uint32_t*)&h1, *(uint32_t*)&h2, *(uint32_t*)&h3);
}

// out = A @ Y1h. Zero-restores g_cnt.
__global__ void spmm2_kernel(float4* __restrict__ out) {
    int row = blockIdx.x * (blockDim.x >> 5) + (threadIdx.x >> 5);
    if (row >= N_NODES) return;
    int lane = threadIdx.x & 31;
    int deg = g_cnt[row];
    if (deg > CAP) deg = CAP;
    const int2* bk = g_bucket + row * CAP;

    float acc[4] = {};
    int e = 0;
    for (; e + 2 <= deg; e += 2) {
        int2 t0 = bk[e], t1 = bk[e + 1];
        uint2 r0 = *(const uint2*)(g_Y1h + (size_t)t0.x * OUT_DIM + lane * 4);
        uint2 r1 = *(const uint2*)(g_Y1h + (size_t)t1.x * OUT_DIM + lane * 4);
        float v0 = __int_as_float(t0.y), v1 = __int_as_float(t1.y);
        float2 a0 = __half22float2(*(__half2*)&r0.x);
        float2 a1 = __half22float2(*(__half2*)&r0.y);
        float2 b0 = __half22float2(*(__half2*)&r1.x);
        float2 b1 = __half22float2(*(__half2*)&r1.y);
        acc[0] = fmaf(v0, a0.x, acc[0]); acc[1] = fmaf(v0, a0.y, acc[1]);
        acc[2] = fmaf(v0, a1.x, acc[2]); acc[3] = fmaf(v0, a1.y, acc[3]);
        acc[0] = fmaf(v1, b0.x, acc[0]); acc[1] = fmaf(v1, b0.y, acc[1]);
        acc[2] = fmaf(v1, b1.x, acc[2]); acc[3] = fmaf(v1, b1.y, acc[3]);
    }
    if (e < deg) {
        int2 t0 = bk[e];
        uint2 r0 = *(const uint2*)(g_Y1h + (size_t)t0.x * OUT_DIM + lane * 4);
        float v0 = __int_as_float(t0.y);
        float2 a0 = __half22float2(*(__half2*)&r0.x);
        float2 a1 = __half22float2(*(__half2*)&r0.y);
        acc[0] = fmaf(v0, a0.x, acc[0]); acc[1] = fmaf(v0, a0.y, acc[1]);
        acc[2] = fmaf(v0, a1.x, acc[2]); acc[3] = fmaf(v0, a1.y, acc[3]);
    }
    out[(size_t)row * 32 + lane] = make_float4(acc[0], acc[1], acc[2], acc[3]);

    if (lane == 0) g_cnt[row] = 0;   // restore invariant for next invocation
}

// ---------------- launch ----------------
extern "C" void kernel_launch(void* const* d_in, const int* in_sizes, int n_in,
                              void* d_out, int out_size) {
    const float* features = (const float*)d_in[0];
    const void*  edge_src = d_in[1];
    const void*  edge_dst = d_in[2];
    const float* edge_val = (const float*)d_in[3];
    const float* W0       = (const float*)d_in[4];
    const float* W1       = (const float*)d_in[5];
    float4*      out      = (float4*)d_out;

    static cudaStream_t s1 = nullptr, s2 = nullptr;
    static cudaEvent_t  ev_fork = nullptr, ev_1 = nullptr, ev_2 = nullptr;
    if (s1 == nullptr) {
        cudaStreamCreateWithFlags(&s1, cudaStreamNonBlocking);
        cudaStreamCreateWithFlags(&s2, cudaStreamNonBlocking);
        cudaEventCreateWithFlags(&ev_fork, cudaEventDisableTiming);
        cudaEventCreateWithFlags(&ev_1,    cudaEventDisableTiming);
        cudaEventCreateWithFlags(&ev_2,    cudaEventDisableTiming);
    }

    // 3-way fork: gemm1 half A (main), gemm1 half B (s1), scatter (s2)
    cudaEventRecord(ev_fork, 0);
    cudaStreamWaitEvent(s1, ev_fork, 0);
    cudaStreamWaitEvent(s2, ev_fork, 0);

    {
        dim3 grid(HIDDEN / 64, G1SPLIT / 64);                       // rows [0, 4992)
        gemm_XW0_kernel<<<grid, 128>>>(features, W0, 0, G1SPLIT);
    }
    {
        dim3 grid(HIDDEN / 64, (N_NODES - G1SPLIT + 63) / 64);      // rows [4992, 10000)
        gemm_XW0_kernel<<<grid, 128, 0, s1>>>(features, W0, G1SPLIT, N_NODES);
    }
    scatter_kernel<<<(N_EDGES + 255) / 256, 256, 0, s2>>>(edge_src, edge_dst, edge_val);

    cudaEventRecord(ev_1, s1);
    cudaEventRecord(ev_2, s2);
    cudaStreamWaitEvent(0, ev_1, 0);
    cudaStreamWaitEvent(0, ev_2, 0);

    // g_Hh = fp16(relu(A @ Y0h))
    spmm1_kernel<<<(N_NODES + 7) / 8, 256>>>();

    // Y1h = Hh @ W1
    {
        dim3 grid(OUT_DIM / 64, (N_NODES + 63) / 64);
        gemm_HW1_kernel<<<grid, 128>>>(W1, N_NODES);
    }

    // out = A @ Y1h  (also zero-restores g_cnt)
    spmm2_kernel<<<(N_NODES + 7) / 8, 256>>>(out);
}

// round 16
// speedup vs baseline: 1.2063x; 1.1331x over previous
#include <cuda_runtime.h>
#include <cuda_fp16.h>
#include <cstdint>

#define N_NODES  10000
#define N_EDGES  320000
#define IN_DIM   256
#define HIDDEN   256
#define OUT_DIM  128
#define CAP      96     // per-node bucket capacity; max degree ~56 (11σ margin)
#define G1SPLIT  4992   // 64-aligned row split for the two gemm1 halves

// ---------------- device scratch (static) ----------------
// g_cnt starts zero (static init); spmm2 re-zeroes it each invocation.
__device__ int    g_cnt[N_NODES];
__device__ int2   g_bucket[N_NODES * CAP];                  // {src, float bits of val}
__device__ __align__(16) __half g_Y0h[N_NODES * HIDDEN];    // fp16(X @ W0)
__device__ __align__(16) __half g_Hh [N_NODES * HIDDEN];    // fp16 relu(A @ Y0)
__device__ __align__(16) __half g_Y1h[N_NODES * OUT_DIM];   // fp16(H @ W1)

// ---------------- bucket scatter (R7-proven) ----------------
__global__ void scatter_kernel(const void* __restrict__ src,
                               const void* __restrict__ dst,
                               const float* __restrict__ val) {
    __shared__ int sh_is64;
    int tid = threadIdx.x;
    if (tid < 32) {
        const int* w = (const int*)src;
        int bad = (w[2 * tid + 1] != 0) || (w[2 * (tid + 32) + 1] != 0);
        int all_zero = __all_sync(0xFFFFFFFFu, !bad);
        if (tid == 0) sh_is64 = all_zero;
    }
    __syncthreads();
    int is64 = sh_is64;

    int e = blockIdx.x * blockDim.x + tid;
    if (e < N_EDGES) {
        int d, s;
        if (is64) {
            d = (int)((const long long*)dst)[e];
            s = (int)((const long long*)src)[e];
        } else {
            d = ((const int*)dst)[e];
            s = ((const int*)src)[e];
        }
        int pos = atomicAdd(&g_cnt[d], 1);
        if (pos < CAP)
            g_bucket[d * CAP + pos] = make_int2(s, __float_as_int(val[e]));
    }
}

// ---------------- tf32 MMA helpers (R5-R15 proven) ----------------
__device__ __forceinline__ uint32_t f2tf32(float x) {
    uint32_t r;
    asm("cvt.rna.tf32.f32 %0, %1;" : "=r"(r) : "f"(x));
    return r;
}

__device__ __forceinline__ void mma_tf32(float* d, const uint32_t* a,
                                         const uint32_t* b, const float* c) {
    asm("mma.sync.aligned.m16n8k8.row.col.f32.tf32.tf32.f32 "
        "{%0,%1,%2,%3},{%4,%5,%6,%7},{%8,%9},{%10,%11,%12,%13};"
        : "=f"(d[0]), "=f"(d[1]), "=f"(d[2]), "=f"(d[3])
        : "r"(a[0]), "r"(a[1]), "r"(a[2]), "r"(a[3]),
          "r"(b[0]), "r"(b[1]),
          "f"(c[0]), "f"(c[1]), "f"(c[2]), "f"(c[3]));
}

#define SA 36   // As[m][k] stride (uint32)
#define SB 72   // Bs[k][n] stride (uint32)

// R9-verbatim compute: 4 warps 2m x 2n, warp tile 32x32, BK=32 (4 x k8 steps)
__device__ __forceinline__ void gemm_compute(const uint32_t* As1, const uint32_t* Bs1,
                                             int wm, int wn, int lane,
                                             float acc[2][4][4]) {
    #pragma unroll
    for (int ks = 0; ks < 4; ks++) {
        int kk = ks * 8;
        uint32_t bf[4][2];
        #pragma unroll
        for (int nf = 0; nf < 4; nf++) {
            int n = wn + nf * 8 + (lane >> 2);
            bf[nf][0] = Bs1[(kk + (lane & 3)) * SB + n];
            bf[nf][1] = Bs1[(kk + 4 + (lane & 3)) * SB + n];
        }
        #pragma unroll
        for (int mf = 0; mf < 2; mf++) {
            int m = wm + mf * 16 + (lane >> 2);
            uint32_t af[4];
            af[0] = As1[m * SA + kk + (lane & 3)];
            af[1] = As1[(m + 8) * SA + kk + (lane & 3)];
            af[2] = As1[m * SA + kk + 4 + (lane & 3)];
            af[3] = As1[(m + 8) * SA + kk + 4 + (lane & 3)];
            #pragma unroll
            for (int nf = 0; nf < 4; nf++)
                mma_tf32(acc[mf][nf], af, bf[nf], acc[mf][nf]);
        }
    }
}

// R9-verbatim epilogue: fp32 acc -> fp16 pairs into C[M][N] (rows < m_end)
__device__ __forceinline__ void gemm_epilogue(__half* __restrict__ C, int m_end, int N,
                                              int bm, int bn, int wm, int wn,
                                              int lane, float acc[2][4][4]) {
    #pragma unroll
    for (int mf = 0; mf < 2; mf++) {
        int r0 = bm + wm + mf * 16 + (lane >> 2);
        #pragma unroll
        for (int nf = 0; nf < 4; nf++) {
            int c0 = bn + wn + nf * 8 + 2 * (lane & 3);
            if (r0 < m_end)
                *(__half2*)&C[(size_t)r0 * N + c0] =
                    __floats2half2_rn(acc[mf][nf][0], acc[mf][nf][1]);
            if (r0 + 8 < m_end)
                *(__half2*)&C[(size_t)(r0 + 8) * N + c0] =
                    __floats2half2_rn(acc[mf][nf][2], acc[mf][nf][3]);
        }
    }
}

// GEMM1 (R15-verbatim): A fp32 rows [row_base,m_end), B fp32 -> Y0h fp16
__global__ __launch_bounds__(128) void gemm_XW0_kernel(const float* __restrict__ A,
                                                       const float* __restrict__ B,
                                                       int row_base, int m_end) {
    const int N = HIDDEN;
    __shared__ __align__(16) uint32_t As[2][64 * SA];
    __shared__ __align__(16) uint32_t Bs[2][32 * SB];

    int tid  = threadIdx.x;
    int lane = tid & 31;
    int wid  = tid >> 5;
    int wm = (wid & 1) * 32;
    int wn = (wid >> 1) * 32;
    int bm = row_base + blockIdx.y * 64;
    int bn = blockIdx.x * 64;

    int a_kf = tid & 7;
    int a_m0 = tid >> 3;
    int b_nq = tid & 15;
    int b_k0 = tid >> 4;

    float acc[2][4][4] = {};
    float4 ar[4], br[4];

    #pragma unroll
    for (int it = 0; it < 4; it++) {
        int gr = bm + a_m0 + it * 16;
        ar[it] = (gr < m_end) ? *(const float4*)&A[(size_t)gr * 256 + a_kf * 4]
                              : make_float4(0.f, 0.f, 0.f, 0.f);
        br[it] = *(const float4*)&B[(size_t)(b_k0 + it * 8) * N + bn + b_nq * 4];
    }
    #pragma unroll
    for (int it = 0; it < 4; it++) {
        int m = a_m0 + it * 16;
        *(uint4*)&As[0][m * SA + a_kf * 4] =
            make_uint4(f2tf32(ar[it].x), f2tf32(ar[it].y),
                       f2tf32(ar[it].z), f2tf32(ar[it].w));
        int k = b_k0 + it * 8;
        *(uint4*)&Bs[0][k * SB + b_nq * 4] =
            make_uint4(f2tf32(br[it].x), f2tf32(br[it].y),
                       f2tf32(br[it].z), f2tf32(br[it].w));
    }
    __syncthreads();

    #pragma unroll
    for (int k0 = 0; k0 < 8; k0++) {
        int cur = k0 & 1;
        if (k0 < 7) {
            int kb = (k0 + 1) * 32;
            #pragma unroll
            for (int it = 0; it < 4; it++) {
                int gr = bm + a_m0 + it * 16;
                ar[it] = (gr < m_end) ? *(const float4*)&A[(size_t)gr * 256 + kb + a_kf * 4]
                                      : make_float4(0.f, 0.f, 0.f, 0.f);
                br[it] = *(const float4*)&B[(size_t)(kb + b_k0 + it * 8) * N + bn + b_nq * 4];
            }
        }

        gemm_compute(As[cur], Bs[cur], wm, wn, lane, acc);

        if (k0 < 7) {
            #pragma unroll
            for (int it = 0; it < 4; it++) {
                int m = a_m0 + it * 16;
                *(uint4*)&As[1 - cur][m * SA + a_kf * 4] =
                    make_uint4(f2tf32(ar[it].x), f2tf32(ar[it].y),
                               f2tf32(ar[it].z), f2tf32(ar[it].w));
                int k = b_k0 + it * 8;
                *(uint4*)&Bs[1 - cur][k * SB + b_nq * 4] =
                    make_uint4(f2tf32(br[it].x), f2tf32(br[it].y),
                               f2tf32(br[it].z), f2tf32(br[it].w));
            }
            __syncthreads();
        }
    }

    gemm_epilogue(g_Y0h, m_end, N, bm, bn, wm, wn, lane, acc);
}

// GEMM2 (R15-verbatim): A fp16 (g_Hh), B fp32 -> Y1h fp16; one sync/iter.
__global__ __launch_bounds__(128) void gemm_HW1_kernel(const float* __restrict__ B, int M) {
    const int N = OUT_DIM;
    __shared__ __align__(16) uint32_t As[2][64 * SA];
    __shared__ __align__(16) uint32_t Bs[2][32 * SB];

    int tid  = threadIdx.x;
    int lane = tid & 31;
    int wid  = tid >> 5;
    int wm = (wid & 1) * 32;
    int wn = (wid >> 1) * 32;
    int bm = blockIdx.y * 64;
    int bn = blockIdx.x * 64;

    int a_kf = tid & 3;
    int a_m0 = tid >> 2;
    int b_nq = tid & 15;
    int b_k0 = tid >> 4;

    float acc[2][4][4] = {};
    uint4  ar[2];
    float4 br[4];

    #pragma unroll
    for (int it = 0; it < 2; it++) {
        int gr = bm + a_m0 + it * 32;
        ar[it] = (gr < M) ? *(const uint4*)&g_Hh[(size_t)gr * 256 + a_kf * 8]
                          : make_uint4(0, 0, 0, 0);
    }
    #pragma unroll
    for (int it = 0; it < 4; it++)
        br[it] = *(const float4*)&B[(size_t)(b_k0 + it * 8) * N + bn + b_nq * 4];

    #pragma unroll
    for (int it = 0; it < 2; it++) {
        int m = a_m0 + it * 32;
        const __half2* hp = (const __half2*)&ar[it];
        float2 f0 = __half22float2(hp[0]);
        float2 f1 = __half22float2(hp[1]);
        float2 f2 = __half22float2(hp[2]);
        float2 f3 = __half22float2(hp[3]);
        *(uint4*)&As[0][m * SA + a_kf * 8] =
            make_uint4(f2tf32(f0.x), f2tf32(f0.y), f2tf32(f1.x), f2tf32(f1.y));
        *(uint4*)&As[0][m * SA + a_kf * 8 + 4] =
            make_uint4(f2tf32(f2.x), f2tf32(f2.y), f2tf32(f3.x), f2tf32(f3.y));
    }
    #pragma unroll
    for (int it = 0; it < 4; it++) {
        int k = b_k0 + it * 8;
        *(uint4*)&Bs[0][k * SB + b_nq * 4] =
            make_uint4(f2tf32(br[it].x), f2tf32(br[it].y),
                       f2tf32(br[it].z), f2tf32(br[it].w));
    }
    __syncthreads();

    #pragma unroll
    for (int k0 = 0; k0 < 8; k0++) {
        int cur = k0 & 1;
        if (k0 < 7) {
            int kb = (k0 + 1) * 32;
            #pragma unroll
            for (int it = 0; it < 2; it++) {
                int gr = bm + a_m0 + it * 32;
                ar[it] = (gr < M) ? *(const uint4*)&g_Hh[(size_t)gr * 256 + kb + a_kf * 8]
                                  : make_uint4(0, 0, 0, 0);
            }
            #pragma unroll
            for (int it = 0; it < 4; it++)
                br[it] = *(const float4*)&B[(size_t)(kb + b_k0 + it * 8) * N + bn + b_nq * 4];
        }

        gemm_compute(As[cur], Bs[cur], wm, wn, lane, acc);

        if (k0 < 7) {
            #pragma unroll
            for (int it = 0; it < 2; it++) {
                int m = a_m0 + it * 32;
                const __half2* hp = (const __half2*)&ar[it];
                float2 f0 = __half22float2(hp[0]);
                float2 f1 = __half22float2(hp[1]);
                float2 f2 = __half22float2(hp[2]);
                float2 f3 = __half22float2(hp[3]);
                *(uint4*)&As[1 - cur][m * SA + a_kf * 8] =
                    make_uint4(f2tf32(f0.x), f2tf32(f0.y), f2tf32(f1.x), f2tf32(f1.y));
                *(uint4*)&As[1 - cur][m * SA + a_kf * 8 + 4] =
                    make_uint4(f2tf32(f2.x), f2tf32(f2.y), f2tf32(f3.x), f2tf32(f3.y));
            }
            #pragma unroll
            for (int it = 0; it < 4; it++) {
                int k = b_k0 + it * 8;
                *(uint4*)&Bs[1 - cur][k * SB + b_nq * 4] =
                    make_uint4(f2tf32(br[it].x), f2tf32(br[it].y),
                               f2tf32(br[it].z), f2tf32(br[it].w));
            }
            __syncthreads();
        }
    }

    gemm_epilogue(g_Y1h, M, N, bm, bn, wm, wn, lane, acc);
}

// ---------------- bucket SpMMs: 4-edge software pipeline ----------------
__device__ __forceinline__ void fma_h8(float* a, uint4 r, float v) {
    float2 f0 = __half22float2(*(__half2*)&r.x);
    float2 f1 = __half22float2(*(__half2*)&r.y);
    float2 f2 = __half22float2(*(__half2*)&r.z);
    float2 f3 = __half22float2(*(__half2*)&r.w);
    a[0] = fmaf(v, f0.x, a[0]); a[1] = fmaf(v, f0.y, a[1]);
    a[2] = fmaf(v, f1.x, a[2]); a[3] = fmaf(v, f1.y, a[3]);
    a[4] = fmaf(v, f2.x, a[4]); a[5] = fmaf(v, f2.y, a[5]);
    a[6] = fmaf(v, f3.x, a[6]); a[7] = fmaf(v, f3.y, a[7]);
}

// g_Hh = fp16(relu(A @ Y0h)); 4-edge unroll, gathers issued before FMAs.
__global__ void spmm1_kernel() {
    int row = blockIdx.x * (blockDim.x >> 5) + (threadIdx.x >> 5);
    if (row >= N_NODES) return;
    int lane = threadIdx.x & 31;
    int deg = g_cnt[row];
    if (deg > CAP) deg = CAP;
    const int2* bk = g_bucket + row * CAP;

    float acc[8] = {};
    int e = 0;

    if (e + 4 <= deg) {
        // prologue: first 4 bucket entries
        int2 t0 = bk[0], t1 = bk[1], t2 = bk[2], t3 = bk[3];
        for (; e + 4 <= deg; ) {
            // issue all 4 gathers (4 outstanding loads)
            uint4 r0 = *(const uint4*)(g_Y0h + (size_t)t0.x * HIDDEN + lane * 8);
            uint4 r1 = *(const uint4*)(g_Y0h + (size_t)t1.x * HIDDEN + lane * 8);
            uint4 r2 = *(const uint4*)(g_Y0h + (size_t)t2.x * HIDDEN + lane * 8);
            uint4 r3 = *(const uint4*)(g_Y0h + (size_t)t3.x * HIDDEN + lane * 8);
            float v0 = __int_as_float(t0.y), v1 = __int_as_float(t1.y);
            float v2 = __int_as_float(t2.y), v3 = __int_as_float(t3.y);
            e += 4;
            // prefetch next 4 bucket entries (overlaps gather latency)
            if (e + 4 <= deg) {
                t0 = bk[e]; t1 = bk[e + 1]; t2 = bk[e + 2]; t3 = bk[e + 3];
            }
            fma_h8(acc, r0, v0);
            fma_h8(acc, r1, v1);
            fma_h8(acc, r2, v2);
            fma_h8(acc, r3, v3);
        }
    }
    for (; e < deg; e++) {
        int2 t = bk[e];
        uint4 r = *(const uint4*)(g_Y0h + (size_t)t.x * HIDDEN + lane * 8);
        fma_h8(acc, r, __int_as_float(t.y));
    }

    #pragma unroll
    for (int i = 0; i < 8; i++) acc[i] = fmaxf(acc[i], 0.f);
    __half2 h0 = __floats2half2_rn(acc[0], acc[1]);
    __half2 h1 = __floats2half2_rn(acc[2], acc[3]);
    __half2 h2 = __floats2half2_rn(acc[4], acc[5]);
    __half2 h3 = __floats2half2_rn(acc[6], acc[7]);
    *(uint4*)&g_Hh[(size_t)row * HIDDEN + lane * 8] =
        make_uint4(*(uint32_t*)&h0, *(uint32_t*)&h1, *(uint32_t*)&h2, *(uint32_t*)&h3);
}

// out = A @ Y1h; 4-edge unroll. Zero-restores g_cnt.
__global__ void spmm2_kernel(float4* __restrict__ out) {
    int row = blockIdx.x * (blockDim.x >> 5) + (threadIdx.x >> 5);
    if (row >= N_NODES) return;
    int lane = threadIdx.x & 31;
    int deg = g_cnt[row];
    if (deg > CAP) deg = CAP;
    const int2* bk = g_bucket + row * CAP;

    float acc[4] = {};
    int e = 0;

    if (e + 4 <= deg) {
        int2 t0 = bk[0], t1 = bk[1], t2 = bk[2], t3 = bk[3];
        for (; e + 4 <= deg; ) {
            uint2 r0 = *(const uint2*)(g_Y1h + (size_t)t0.x * OUT_DIM + lane * 4);
            uint2 r1 = *(const uint2*)(g_Y1h + (size_t)t1.x * OUT_DIM + lane * 4);
            uint2 r2 = *(const uint2*)(g_Y1h + (size_t)t2.x * OUT_DIM + lane * 4);
            uint2 r3 = *(const uint2*)(g_Y1h + (size_t)t3.x * OUT_DIM + lane * 4);
            float v0 = __int_as_float(t0.y), v1 = __int_as_float(t1.y);
            float v2 = __int_as_float(t2.y), v3 = __int_as_float(t3.y);
            e += 4;
            if (e + 4 <= deg) {
                t0 = bk[e]; t1 = bk[e + 1]; t2 = bk[e + 2]; t3 = bk[e + 3];
            }
            float2 a0 = __half22float2(*(__half2*)&r0.x);
            float2 a1 = __half22float2(*(__half2*)&r0.y);
            acc[0] = fmaf(v0, a0.x, acc[0]); acc[1] = fmaf(v0, a0.y, acc[1]);
            acc[2] = fmaf(v0, a1.x, acc[2]); acc[3] = fmaf(v0, a1.y, acc[3]);
            a0 = __half22float2(*(__half2*)&r1.x);
            a1 = __half22float2(*(__half2*)&r1.y);
            acc[0] = fmaf(v1, a0.x, acc[0]); acc[1] = fmaf(v1, a0.y, acc[1]);
            acc[2] = fmaf(v1, a1.x, acc[2]); acc[3] = fmaf(v1, a1.y, acc[3]);
            a0 = __half22float2(*(__half2*)&r2.x);
            a1 = __half22float2(*(__half2*)&r2.y);
            acc[0] = fmaf(v2, a0.x, acc[0]); acc[1] = fmaf(v2, a0.y, acc[1]);
            acc[2] = fmaf(v2, a1.x, acc[2]); acc[3] = fmaf(v2, a1.y, acc[3]);
            a0 = __half22float2(*(__half2*)&r3.x);
            a1 = __half22float2(*(__half2*)&r3.y);
            acc[0] = fmaf(v3, a0.x, acc[0]); acc[1] = fmaf(v3, a0.y, acc[1]);
            acc[2] = fmaf(v3, a1.x, acc[2]); acc[3] = fmaf(v3, a1.y, acc[3]);
        }
    }
    for (; e < deg; e++) {
        int2 t = bk[e];
        uint2 r = *(const uint2*)(g_Y1h + (size_t)t.x * OUT_DIM + lane * 4);
        float v = __int_as_float(t.y);
        float2 a0 = __half22float2(*(__half2*)&r.x);
        float2 a1 = __half22float2(*(__half2*)&r.y);
        acc[0] = fmaf(v, a0.x, acc[0]); acc[1] = fmaf(v, a0.y, acc[1]);
        acc[2] = fmaf(v, a1.x, acc[2]); acc[3] = fmaf(v, a1.y, acc[3]);
    }
    out[(size_t)row * 32 + lane] = make_float4(acc[0], acc[1], acc[2], acc[3]);

    if (lane == 0) g_cnt[row] = 0;   // restore invariant for next invocation
}

// ---------------- launch ----------------
extern "C" void kernel_launch(void* const* d_in, const int* in_sizes, int n_in,
                              void* d_out, int out_size) {
    const float* features = (const float*)d_in[0];
    const void*  edge_src = d_in[1];
    const void*  edge_dst = d_in[2];
    const float* edge_val = (const float*)d_in[3];
    const float* W0       = (const float*)d_in[4];
    const float* W1       = (const float*)d_in[5];
    float4*      out      = (float4*)d_out;

    static cudaStream_t s1 = nullptr, s2 = nullptr;
    static cudaEvent_t  ev_fork = nullptr, ev_1 = nullptr, ev_2 = nullptr;
    if (s1 == nullptr) {
        cudaStreamCreateWithFlags(&s1, cudaStreamNonBlocking);
        cudaStreamCreateWithFlags(&s2, cudaStreamNonBlocking);
        cudaEventCreateWithFlags(&ev_fork, cudaEventDisableTiming);
        cudaEventCreateWithFlags(&ev_1,    cudaEventDisableTiming);
        cudaEventCreateWithFlags(&ev_2,    cudaEventDisableTiming);
    }

    // 3-way fork: gemm1 half A (main), gemm1 half B (s1), scatter (s2)
    cudaEventRecord(ev_fork, 0);
    cudaStreamWaitEvent(s1, ev_fork, 0);
    cudaStreamWaitEvent(s2, ev_fork, 0);

    {
        dim3 grid(HIDDEN / 64, G1SPLIT / 64);
        gemm_XW0_kernel<<<grid, 128>>>(features, W0, 0, G1SPLIT);
    }
    {
        dim3 grid(HIDDEN / 64, (N_NODES - G1SPLIT + 63) / 64);
        gemm_XW0_kernel<<<grid, 128, 0, s1>>>(features, W0, G1SPLIT, N_NODES);
    }
    scatter_kernel<<<(N_EDGES + 255) / 256, 256, 0, s2>>>(edge_src, edge_dst, edge_val);

    cudaEventRecord(ev_1, s1);
    cudaEventRecord(ev_2, s2);
    cudaStreamWaitEvent(0, ev_1, 0);
    cudaStreamWaitEvent(0, ev_2, 0);

    // g_Hh = fp16(relu(A @ Y0h))
    spmm1_kernel<<<(N_NODES + 7) / 8, 256>>>();

    // Y1h = Hh @ W1
    {
        dim3 grid(OUT_DIM / 64, (N_NODES + 63) / 64);
        gemm_HW1_kernel<<<grid, 128>>>(W1, N_NODES);
    }

    // out = A @ Y1h  (also zero-restores g_cnt)
    spmm2_kernel<<<(N_NODES + 7) / 8, 256>>>(out);
}